// round 1
// baseline (speedup 1.0000x reference)
#include <cuda_runtime.h>
#include <math.h>
#include <stdint.h>

#define HIDDEN   2048
#define HEADS    16
#define HEAD_DIM 128
#define HALF_DIM 64
#define BATCH    2
#define SQ       2048
#define SK       2048
#define MROWS    (BATCH * SQ)   // 4096

// ---------------- scratch (device globals; no allocation allowed) ----------------
__device__ float g_Q[BATCH * SQ * HIDDEN];
__device__ float g_K[BATCH * SK * HIDDEN];
__device__ float g_V[BATCH * SK * HIDDEN];
__device__ float g_O[BATCH * SQ * HIDDEN];
__device__ float g_cos[SK * HALF_DIM];
__device__ float g_sin[SK * HALF_DIM];

// ---------------- RoPE table (double precision, computed once per launch) --------
__global__ void rope_table_kernel() {
    int i = blockIdx.x * blockDim.x + threadIdx.x;
    if (i >= SK * HALF_DIM) return;
    int s = i / HALF_DIM;
    int f = i - s * HALF_DIM;
    double inv = pow(10000.0, -(double)f / (double)HALF_DIM);
    double ang = (double)s * inv;
    g_cos[i] = (float)cos(ang);
    g_sin[i] = (float)sin(ang);
}

// ---------------- generic NT SGEMM: C[M,N] = A[M,K] * B[N,K]^T -------------------
// 128x128 block tile, BK=8, 256 threads, 8x8 per-thread micro-tile.
__global__ __launch_bounds__(256) void gemm_nt_kernel(
    const float* __restrict__ A, const float* __restrict__ Bm,
    float* __restrict__ C, int M, int N, int K)
{
    __shared__ float As[8][128];
    __shared__ float Bs[8][128];

    const int tid = threadIdx.x;
    const int m0 = blockIdx.y * 128;
    const int n0 = blockIdx.x * 128;

    const int lr = tid >> 1;            // 0..127 : row within tile for loading
    const int lk = (tid & 1) * 4;       // 0 or 4 : k offset within BK

    const int rg = (tid >> 4) * 8;      // 0..120 step 8 : output row group
    const int cg = (tid & 15) * 8;      // 0..120 step 8 : output col group

    float acc[8][8];
#pragma unroll
    for (int i = 0; i < 8; i++)
#pragma unroll
        for (int j = 0; j < 8; j++) acc[i][j] = 0.f;

    const float* Arow = A + (size_t)(m0 + lr) * K;
    const float* Brow = Bm + (size_t)(n0 + lr) * K;

    for (int k0 = 0; k0 < K; k0 += 8) {
        float4 av = *(const float4*)(Arow + k0 + lk);
        float4 bv = *(const float4*)(Brow + k0 + lk);
        As[lk + 0][lr] = av.x; As[lk + 1][lr] = av.y;
        As[lk + 2][lr] = av.z; As[lk + 3][lr] = av.w;
        Bs[lk + 0][lr] = bv.x; Bs[lk + 1][lr] = bv.y;
        Bs[lk + 2][lr] = bv.z; Bs[lk + 3][lr] = bv.w;
        __syncthreads();

#pragma unroll
        for (int kk = 0; kk < 8; kk++) {
            float a[8], b[8];
            *(float4*)(a)     = *(const float4*)&As[kk][rg];
            *(float4*)(a + 4) = *(const float4*)&As[kk][rg + 4];
            *(float4*)(b)     = *(const float4*)&Bs[kk][cg];
            *(float4*)(b + 4) = *(const float4*)&Bs[kk][cg + 4];
#pragma unroll
            for (int i = 0; i < 8; i++)
#pragma unroll
                for (int j = 0; j < 8; j++)
                    acc[i][j] += a[i] * b[j];
        }
        __syncthreads();
    }

#pragma unroll
    for (int i = 0; i < 8; i++) {
        float* crow = C + (size_t)(m0 + rg + i) * N + n0 + cg;
        float4 v0 = make_float4(acc[i][0], acc[i][1], acc[i][2], acc[i][3]);
        float4 v1 = make_float4(acc[i][4], acc[i][5], acc[i][6], acc[i][7]);
        *(float4*)(crow)     = v0;
        *(float4*)(crow + 4) = v1;
    }
}

// ---------------- RoPE apply (in-place, pair-interleaved) ------------------------
__global__ void rope_apply_kernel(float* __restrict__ buf, int S, long total_pairs) {
    long i = (long)blockIdx.x * blockDim.x + threadIdx.x;
    if (i >= total_pairs) return;
    int f = (int)(i & (HALF_DIM - 1));
    long t = i >> 6;                       // ((b*S + s)*HEADS + h)
    int s = (int)((t / HEADS) % S);
    float c  = g_cos[s * HALF_DIM + f];
    float sn = g_sin[s * HALF_DIM + f];
    float2* p = (float2*)(buf + t * (size_t)HEAD_DIM) + f;
    float2 xv = *p;
    float2 ov;
    ov.x = xv.x * c - xv.y * sn;
    ov.y = xv.x * sn + xv.y * c;
    *p = ov;
}

// ---------------- flash attention ------------------------------------------------
// Grid: (B*HEADS, SQ/64). Block 256 threads (16x16).
// Per thread: 4x4 of the 64x64 score tile; 4 rows x 8 cols of the O tile.
#define FA_BM 64
#define FA_BN 64
#define QS_STRIDE 68   // 64 + pad, multiple of 4 (float4-aligned rows)
#define PS_STRIDE 68

#define FA_SMEM_FLOATS (2 * HEAD_DIM * QS_STRIDE + FA_BN * HEAD_DIM + FA_BM * PS_STRIDE)
#define FA_SMEM_BYTES  (FA_SMEM_FLOATS * 4)

__global__ __launch_bounds__(256) void flash_attn_kernel(const int* __restrict__ mask) {
    extern __shared__ float sm[];
    float* Qs = sm;                                   // [128][68]  (d-major)
    float* Ks = Qs + HEAD_DIM * QS_STRIDE;            // [128][68]  (d-major)
    float* Vs = Ks + HEAD_DIM * QS_STRIDE;            // [64][128]  (row-major)
    float* Ps = Vs + FA_BN * HEAD_DIM;                // [64][68]
    __shared__ int ms[FA_BN];

    const int bh = blockIdx.x;
    const int b  = bh / HEADS;
    const int h  = bh - b * HEADS;
    const int q0 = blockIdx.y * FA_BM;
    const int tid = threadIdx.x;
    const int ty = tid >> 4, tx = tid & 15;
    const int r0 = ty * 4;        // score/O row group
    const int cS = tx * 4;        // score col group
    const int cO = tx * 8;        // O col group
    const float rscale = 0.08838834764831845f;  // 1/sqrt(128)

    // --- load Q tile, transposed to d-major, pre-scaled ---
    for (int e = tid; e < FA_BM * (HEAD_DIM / 4); e += 256) {
        int r  = e >> 5;               // 32 float4 per row
        int d4 = (e & 31) * 4;
        const float* src = g_Q + ((size_t)((b * SQ + q0 + r) * HEADS + h)) * HEAD_DIM + d4;
        float4 v = *(const float4*)src;
        Qs[(d4 + 0) * QS_STRIDE + r] = v.x * rscale;
        Qs[(d4 + 1) * QS_STRIDE + r] = v.y * rscale;
        Qs[(d4 + 2) * QS_STRIDE + r] = v.z * rscale;
        Qs[(d4 + 3) * QS_STRIDE + r] = v.w * rscale;
    }

    float m_i[4], l_i[4], acc[4][8];
#pragma unroll
    for (int i = 0; i < 4; i++) {
        m_i[i] = -1e30f; l_i[i] = 0.f;
#pragma unroll
        for (int j = 0; j < 8; j++) acc[i][j] = 0.f;
    }

    for (int k0 = 0; k0 < SK; k0 += FA_BN) {
        // --- load K (transposed) and V (natural), mask ---
        for (int e = tid; e < FA_BN * (HEAD_DIM / 4); e += 256) {
            int c  = e >> 5;
            int d4 = (e & 31) * 4;
            size_t base = ((size_t)((b * SK + k0 + c) * HEADS + h)) * HEAD_DIM + d4;
            float4 kv = *(const float4*)(g_K + base);
            Ks[(d4 + 0) * QS_STRIDE + c] = kv.x;
            Ks[(d4 + 1) * QS_STRIDE + c] = kv.y;
            Ks[(d4 + 2) * QS_STRIDE + c] = kv.z;
            Ks[(d4 + 3) * QS_STRIDE + c] = kv.w;
            float4 vv = *(const float4*)(g_V + base);
            *(float4*)&Vs[c * HEAD_DIM + d4] = vv;
        }
        if (tid < FA_BN) ms[tid] = mask[b * SK + k0 + tid];
        __syncthreads();

        // --- S = Q K^T (scaled) ---
        float s_[4][4];
#pragma unroll
        for (int i = 0; i < 4; i++)
#pragma unroll
            for (int j = 0; j < 4; j++) s_[i][j] = 0.f;

#pragma unroll 8
        for (int d = 0; d < HEAD_DIM; d++) {
            float4 qa = *(const float4*)(Qs + d * QS_STRIDE + r0);
            float4 kb = *(const float4*)(Ks + d * QS_STRIDE + cS);
            float qv[4] = {qa.x, qa.y, qa.z, qa.w};
            float kv[4] = {kb.x, kb.y, kb.z, kb.w};
#pragma unroll
            for (int i = 0; i < 4; i++)
#pragma unroll
                for (int j = 0; j < 4; j++)
                    s_[i][j] += qv[i] * kv[j];
        }

        // --- mask ---
#pragma unroll
        for (int j = 0; j < 4; j++) {
            if (ms[cS + j] == 0) {
#pragma unroll
                for (int i = 0; i < 4; i++) s_[i][j] = -1e30f;
            }
        }

        // --- online softmax update ---
        float tm[4];
#pragma unroll
        for (int i = 0; i < 4; i++) {
            tm[i] = fmaxf(fmaxf(s_[i][0], s_[i][1]), fmaxf(s_[i][2], s_[i][3]));
#pragma unroll
            for (int off = 1; off < 16; off <<= 1)
                tm[i] = fmaxf(tm[i], __shfl_xor_sync(0xffffffffu, tm[i], off));
        }

        float p[4][4], rs[4];
#pragma unroll
        for (int i = 0; i < 4; i++) {
            float mn   = fmaxf(m_i[i], tm[i]);
            float corr = expf(m_i[i] - mn);
            m_i[i] = mn;
            float r = 0.f;
#pragma unroll
            for (int j = 0; j < 4; j++) {
                p[i][j] = expf(s_[i][j] - mn);
                r += p[i][j];
            }
            rs[i] = r;
#pragma unroll
            for (int off = 1; off < 16; off <<= 1)
                rs[i] += __shfl_xor_sync(0xffffffffu, rs[i], off);
            l_i[i] = l_i[i] * corr + rs[i];
#pragma unroll
            for (int j = 0; j < 8; j++) acc[i][j] *= corr;
        }

        // --- stage P through shared ---
#pragma unroll
        for (int i = 0; i < 4; i++) {
            float4 pv = make_float4(p[i][0], p[i][1], p[i][2], p[i][3]);
            *(float4*)&Ps[(r0 + i) * PS_STRIDE + cS] = pv;
        }
        __syncthreads();

        // --- O += P V ---
#pragma unroll 1
        for (int c = 0; c < FA_BN; c += 4) {
            float pi[4][4];
#pragma unroll
            for (int i = 0; i < 4; i++) {
                float4 pr = *(const float4*)(Ps + (r0 + i) * PS_STRIDE + c);
                pi[i][0] = pr.x; pi[i][1] = pr.y; pi[i][2] = pr.z; pi[i][3] = pr.w;
            }
#pragma unroll
            for (int u = 0; u < 4; u++) {
                float4 va = *(const float4*)(Vs + (c + u) * HEAD_DIM + cO);
                float4 vb = *(const float4*)(Vs + (c + u) * HEAD_DIM + cO + 4);
#pragma unroll
                for (int i = 0; i < 4; i++) {
                    float pv = pi[i][u];
                    acc[i][0] += pv * va.x; acc[i][1] += pv * va.y;
                    acc[i][2] += pv * va.z; acc[i][3] += pv * va.w;
                    acc[i][4] += pv * vb.x; acc[i][5] += pv * vb.y;
                    acc[i][6] += pv * vb.z; acc[i][7] += pv * vb.w;
                }
            }
        }
        __syncthreads();
    }

    // --- epilogue: O /= l, write [B,SQ,H,D] ---
#pragma unroll
    for (int i = 0; i < 4; i++) {
        float inv = 1.f / l_i[i];
        float* dst = g_O + ((size_t)((b * SQ + q0 + r0 + i) * HEADS + h)) * HEAD_DIM + cO;
        float4 v0 = make_float4(acc[i][0] * inv, acc[i][1] * inv, acc[i][2] * inv, acc[i][3] * inv);
        float4 v1 = make_float4(acc[i][4] * inv, acc[i][5] * inv, acc[i][6] * inv, acc[i][7] * inv);
        *(float4*)(dst)     = v0;
        *(float4*)(dst + 4) = v1;
    }
}

// ---------------- launch ---------------------------------------------------------
extern "C" void kernel_launch(void* const* d_in, const int* in_sizes, int n_in,
                              void* d_out, int out_size) {
    const float* x    = (const float*)d_in[0];
    const float* enc  = (const float*)d_in[1];
    const int*   mask = (const int*)d_in[2];
    const float* Wq   = (const float*)d_in[3];
    const float* Wk   = (const float*)d_in[4];
    const float* Wv   = (const float*)d_in[5];
    const float* Wo   = (const float*)d_in[6];
    float* out = (float*)d_out;

    float *q, *k, *v, *o;
    cudaGetSymbolAddress((void**)&q, g_Q);
    cudaGetSymbolAddress((void**)&k, g_K);
    cudaGetSymbolAddress((void**)&v, g_V);
    cudaGetSymbolAddress((void**)&o, g_O);

    // RoPE tables
    rope_table_kernel<<<(SK * HALF_DIM + 255) / 256, 256>>>();

    // Projections
    dim3 gg(HIDDEN / 128, MROWS / 128);   // (16, 32)
    gemm_nt_kernel<<<gg, 256>>>(x,   Wq, q, MROWS, HIDDEN, HIDDEN);
    gemm_nt_kernel<<<gg, 256>>>(enc, Wk, k, MROWS, HIDDEN, HIDDEN);
    gemm_nt_kernel<<<gg, 256>>>(enc, Wv, v, MROWS, HIDDEN, HIDDEN);

    // RoPE on Q, K
    long pairs = (long)BATCH * SQ * HEADS * HALF_DIM;
    int rb = (int)((pairs + 255) / 256);
    rope_apply_kernel<<<rb, 256>>>(q, SQ, pairs);
    rope_apply_kernel<<<rb, 256>>>(k, SK, pairs);

    // Flash attention
    cudaFuncSetAttribute(flash_attn_kernel,
                         cudaFuncAttributeMaxDynamicSharedMemorySize, FA_SMEM_BYTES);
    dim3 ga(BATCH * HEADS, SQ / FA_BM);   // (32, 32)
    flash_attn_kernel<<<ga, 256, FA_SMEM_BYTES>>>(mask);

    // Output projection
    gemm_nt_kernel<<<gg, 256>>>(o, Wo, out, MROWS, HIDDEN, HIDDEN);
}

// round 4
// speedup vs baseline: 1.6379x; 1.6379x over previous
#include <cuda_runtime.h>
#include <math.h>
#include <stdint.h>

#define HIDDEN   2048
#define HEADS    16
#define HEAD_DIM 128
#define HALF_DIM 64
#define BATCH    2
#define SQ       2048
#define SK       2048
#define MROWS    (BATCH * SQ)   // 4096

// ---------------- scratch (device globals; no allocation allowed) ----------------
__device__ float g_Q[BATCH * SQ * HIDDEN];
__device__ float g_K[BATCH * SK * HIDDEN];
__device__ float g_V[BATCH * SK * HIDDEN];
__device__ float g_O[BATCH * SQ * HIDDEN];
__device__ float g_cos[SK * HALF_DIM];
__device__ float g_sin[SK * HALF_DIM];

// ================= helpers =================
__device__ __forceinline__ uint32_t smem_u32(const void* p) {
    uint32_t a;
    asm("{ .reg .u64 t; cvta.to.shared.u64 t, %1; cvt.u32.u64 %0, t; }" : "=r"(a) : "l"(p));
    return a;
}
__device__ __forceinline__ void cp16(uint32_t dst, const void* src) {
    asm volatile("cp.async.cg.shared.global [%0], [%1], 16;" :: "r"(dst), "l"(src));
}
__device__ __forceinline__ float to_tf32(float x) {
    float y;
    asm("cvt.rna.tf32.f32 %0, %1;" : "=f"(y) : "f"(x));
    return y;
}
__device__ __forceinline__ void mma_tf32(float* c, const float* a, const float* b) {
    asm volatile(
        "mma.sync.aligned.m16n8k8.row.col.f32.tf32.tf32.f32 "
        "{%0,%1,%2,%3}, {%4,%5,%6,%7}, {%8,%9}, {%0,%1,%2,%3};"
        : "+f"(c[0]), "+f"(c[1]), "+f"(c[2]), "+f"(c[3])
        : "f"(a[0]), "f"(a[1]), "f"(a[2]), "f"(a[3]),
          "f"(b[0]), "f"(b[1]));
}

// ---------------- RoPE table ----------------
__global__ void rope_table_kernel() {
    int i = blockIdx.x * blockDim.x + threadIdx.x;
    if (i >= SK * HALF_DIM) return;
    int s = i / HALF_DIM;
    int f = i - s * HALF_DIM;
    double inv = pow(10000.0, -(double)f / (double)HALF_DIM);
    double ang = (double)s * inv;
    g_cos[i] = (float)cos(ang);
    g_sin[i] = (float)sin(ang);
}

// ================= tf32 mma.sync GEMM: C[M,N] = A[M,K] * B[N,K]^T ===============
// CTA tile 128x128, BK=32, 8 warps (warp tile 32x64), double-buffered cp.async.
#define GM_TM 128
#define GM_TN 128
#define GM_TK 32
#define GM_LDS 36                            // smem row stride (floats), 144B
#define GM_STG (GM_TM * GM_LDS)              // floats per tile stage
#define GM_SMEM (4 * GM_STG * 4)             // A/B x 2 stages, bytes (73728)

__global__ __launch_bounds__(256) void gemm_mma_kernel(
    const float* __restrict__ A, const float* __restrict__ Bm,
    float* __restrict__ C, int M, int N, int K)
{
    extern __shared__ float sm[];
    float* As = sm;                 // [2][128][36]
    float* Bs = sm + 2 * GM_STG;    // [2][128][36]

    const int tid = threadIdx.x;
    const int wid = tid >> 5;
    const int lane = tid & 31;
    const int qr = lane >> 2;       // 0..7
    const int qc = lane & 3;        // 0..3
    const int m0 = blockIdx.y * GM_TM;
    const int n0 = blockIdx.x * GM_TN;
    const int wm = (wid & 3) * 32;  // warp M offset within tile
    const int wn = (wid >> 2) * 64; // warp N offset within tile

    const uint32_t sa = smem_u32(As);
    const uint32_t sb = smem_u32(Bs);

    float acc[2][8][4];
#pragma unroll
    for (int i = 0; i < 2; i++)
#pragma unroll
        for (int j = 0; j < 8; j++)
#pragma unroll
            for (int t = 0; t < 4; t++) acc[i][j][t] = 0.f;

    // ---- stage loader: 128 rows A + 128 rows B, 8 x 16B chunks per row ----
    auto load_stage = [&](int st, int kk) {
        uint32_t ab = sa + st * GM_STG * 4;
        uint32_t bb = sb + st * GM_STG * 4;
#pragma unroll
        for (int c = 0; c < 4; c++) {        // 1024 chunks / 256 threads
            int e = tid + c * 256;
            int r = e >> 3, cx = e & 7;
            cp16(ab + r * 144 + cx * 16, A + (size_t)(m0 + r) * K + kk + cx * 4);
        }
#pragma unroll
        for (int c = 0; c < 4; c++) {
            int e = tid + c * 256;
            int r = e >> 3, cx = e & 7;
            cp16(bb + r * 144 + cx * 16, Bm + (size_t)(n0 + r) * K + kk + cx * 4);
        }
    };

    const int ITERS = K / GM_TK;   // 64
    load_stage(0, 0);
    asm volatile("cp.async.commit_group;");

    for (int it = 0; it < ITERS; it++) {
        if (it + 1 < ITERS) {
            load_stage((it + 1) & 1, (it + 1) * GM_TK);
            asm volatile("cp.async.commit_group;");
            asm volatile("cp.async.wait_group 1;" ::: "memory");
        } else {
            asm volatile("cp.async.wait_group 0;" ::: "memory");
        }
        __syncthreads();

        const float* at = As + (it & 1) * GM_STG;
        const float* bt = Bs + (it & 1) * GM_STG;

#pragma unroll
        for (int s = 0; s < 4; s++) {
            int kb = s * 8;
            float af[2][4], bf[8][2];
#pragma unroll
            for (int i = 0; i < 2; i++) {
                const float* p = at + (wm + i * 16 + qr) * GM_LDS + kb + qc;
                af[i][0] = to_tf32(p[0]);
                af[i][1] = to_tf32(p[8 * GM_LDS]);
                af[i][2] = to_tf32(p[4]);
                af[i][3] = to_tf32(p[8 * GM_LDS + 4]);
            }
#pragma unroll
            for (int j = 0; j < 8; j++) {
                const float* p = bt + (wn + j * 8 + qr) * GM_LDS + kb + qc;
                bf[j][0] = to_tf32(p[0]);
                bf[j][1] = to_tf32(p[4]);
            }
#pragma unroll
            for (int i = 0; i < 2; i++)
#pragma unroll
                for (int j = 0; j < 8; j++)
                    mma_tf32(acc[i][j], af[i], bf[j]);
        }
        __syncthreads();
    }

    // ---- epilogue: direct STG.64 per fragment half ----
#pragma unroll
    for (int i = 0; i < 2; i++) {
        int rlo = m0 + wm + i * 16 + qr;
#pragma unroll
        for (int j = 0; j < 8; j++) {
            int col = n0 + wn + j * 8 + qc * 2;
            float2 v0 = make_float2(acc[i][j][0], acc[i][j][1]);
            float2 v1 = make_float2(acc[i][j][2], acc[i][j][3]);
            *(float2*)(C + (size_t)rlo * N + col)       = v0;
            *(float2*)(C + (size_t)(rlo + 8) * N + col) = v1;
        }
    }
}

// ---------------- RoPE apply (in-place, pair-interleaved) ------------------------
__global__ void rope_apply_kernel(float* __restrict__ buf, int S, long total_pairs) {
    long i = (long)blockIdx.x * blockDim.x + threadIdx.x;
    if (i >= total_pairs) return;
    int f = (int)(i & (HALF_DIM - 1));
    long t = i >> 6;
    int s = (int)((t / HEADS) % S);
    float c  = g_cos[s * HALF_DIM + f];
    float sn = g_sin[s * HALF_DIM + f];
    float2* p = (float2*)(buf + t * (size_t)HEAD_DIM) + f;
    float2 xv = *p;
    float2 ov;
    ov.x = xv.x * c - xv.y * sn;
    ov.y = xv.x * sn + xv.y * c;
    *p = ov;
}

// ---------------- flash attention (SIMT fp32, unchanged) -------------------------
#define FA_BM 64
#define FA_BN 64
#define QS_STRIDE 68
#define PS_STRIDE 68
#define FA_SMEM_FLOATS (2 * HEAD_DIM * QS_STRIDE + FA_BN * HEAD_DIM + FA_BM * PS_STRIDE)
#define FA_SMEM_BYTES  (FA_SMEM_FLOATS * 4)

__global__ __launch_bounds__(256) void flash_attn_kernel(const int* __restrict__ mask) {
    extern __shared__ float sm[];
    float* Qs = sm;
    float* Ks = Qs + HEAD_DIM * QS_STRIDE;
    float* Vs = Ks + HEAD_DIM * QS_STRIDE;
    float* Ps = Vs + FA_BN * HEAD_DIM;
    __shared__ int ms[FA_BN];

    const int bh = blockIdx.x;
    const int b  = bh / HEADS;
    const int h  = bh - b * HEADS;
    const int q0 = blockIdx.y * FA_BM;
    const int tid = threadIdx.x;
    const int ty = tid >> 4, tx = tid & 15;
    const int r0 = ty * 4;
    const int cS = tx * 4;
    const int cO = tx * 8;
    const float rscale = 0.08838834764831845f;

    for (int e = tid; e < FA_BM * (HEAD_DIM / 4); e += 256) {
        int r  = e >> 5;
        int d4 = (e & 31) * 4;
        const float* src = g_Q + ((size_t)((b * SQ + q0 + r) * HEADS + h)) * HEAD_DIM + d4;
        float4 v = *(const float4*)src;
        Qs[(d4 + 0) * QS_STRIDE + r] = v.x * rscale;
        Qs[(d4 + 1) * QS_STRIDE + r] = v.y * rscale;
        Qs[(d4 + 2) * QS_STRIDE + r] = v.z * rscale;
        Qs[(d4 + 3) * QS_STRIDE + r] = v.w * rscale;
    }

    float m_i[4], l_i[4], acc[4][8];
#pragma unroll
    for (int i = 0; i < 4; i++) {
        m_i[i] = -1e30f; l_i[i] = 0.f;
#pragma unroll
        for (int j = 0; j < 8; j++) acc[i][j] = 0.f;
    }

    for (int k0 = 0; k0 < SK; k0 += FA_BN) {
        for (int e = tid; e < FA_BN * (HEAD_DIM / 4); e += 256) {
            int c  = e >> 5;
            int d4 = (e & 31) * 4;
            size_t base = ((size_t)((b * SK + k0 + c) * HEADS + h)) * HEAD_DIM + d4;
            float4 kv = *(const float4*)(g_K + base);
            Ks[(d4 + 0) * QS_STRIDE + c] = kv.x;
            Ks[(d4 + 1) * QS_STRIDE + c] = kv.y;
            Ks[(d4 + 2) * QS_STRIDE + c] = kv.z;
            Ks[(d4 + 3) * QS_STRIDE + c] = kv.w;
            float4 vv = *(const float4*)(g_V + base);
            *(float4*)&Vs[c * HEAD_DIM + d4] = vv;
        }
        if (tid < FA_BN) ms[tid] = mask[b * SK + k0 + tid];
        __syncthreads();

        float s_[4][4];
#pragma unroll
        for (int i = 0; i < 4; i++)
#pragma unroll
            for (int j = 0; j < 4; j++) s_[i][j] = 0.f;

#pragma unroll 8
        for (int d = 0; d < HEAD_DIM; d++) {
            float4 qa = *(const float4*)(Qs + d * QS_STRIDE + r0);
            float4 kb = *(const float4*)(Ks + d * QS_STRIDE + cS);
            float qv[4] = {qa.x, qa.y, qa.z, qa.w};
            float kv[4] = {kb.x, kb.y, kb.z, kb.w};
#pragma unroll
            for (int i = 0; i < 4; i++)
#pragma unroll
                for (int j = 0; j < 4; j++)
                    s_[i][j] += qv[i] * kv[j];
        }

#pragma unroll
        for (int j = 0; j < 4; j++) {
            if (ms[cS + j] == 0) {
#pragma unroll
                for (int i = 0; i < 4; i++) s_[i][j] = -1e30f;
            }
        }

        float tm[4];
#pragma unroll
        for (int i = 0; i < 4; i++) {
            tm[i] = fmaxf(fmaxf(s_[i][0], s_[i][1]), fmaxf(s_[i][2], s_[i][3]));
#pragma unroll
            for (int off = 1; off < 16; off <<= 1)
                tm[i] = fmaxf(tm[i], __shfl_xor_sync(0xffffffffu, tm[i], off));
        }

        float p[4][4], rs[4];
#pragma unroll
        for (int i = 0; i < 4; i++) {
            float mn   = fmaxf(m_i[i], tm[i]);
            float corr = expf(m_i[i] - mn);
            m_i[i] = mn;
            float r = 0.f;
#pragma unroll
            for (int j = 0; j < 4; j++) {
                p[i][j] = expf(s_[i][j] - mn);
                r += p[i][j];
            }
            rs[i] = r;
#pragma unroll
            for (int off = 1; off < 16; off <<= 1)
                rs[i] += __shfl_xor_sync(0xffffffffu, rs[i], off);
            l_i[i] = l_i[i] * corr + rs[i];
#pragma unroll
            for (int j = 0; j < 8; j++) acc[i][j] *= corr;
        }

#pragma unroll
        for (int i = 0; i < 4; i++) {
            float4 pv = make_float4(p[i][0], p[i][1], p[i][2], p[i][3]);
            *(float4*)&Ps[(r0 + i) * PS_STRIDE + cS] = pv;
        }
        __syncthreads();

#pragma unroll 1
        for (int c = 0; c < FA_BN; c += 4) {
            float pi[4][4];
#pragma unroll
            for (int i = 0; i < 4; i++) {
                float4 pr = *(const float4*)(Ps + (r0 + i) * PS_STRIDE + c);
                pi[i][0] = pr.x; pi[i][1] = pr.y; pi[i][2] = pr.z; pi[i][3] = pr.w;
            }
#pragma unroll
            for (int u = 0; u < 4; u++) {
                float4 va = *(const float4*)(Vs + (c + u) * HEAD_DIM + cO);
                float4 vb = *(const float4*)(Vs + (c + u) * HEAD_DIM + cO + 4);
#pragma unroll
                for (int i = 0; i < 4; i++) {
                    float pv = pi[i][u];
                    acc[i][0] += pv * va.x; acc[i][1] += pv * va.y;
                    acc[i][2] += pv * va.z; acc[i][3] += pv * va.w;
                    acc[i][4] += pv * vb.x; acc[i][5] += pv * vb.y;
                    acc[i][6] += pv * vb.z; acc[i][7] += pv * vb.w;
                }
            }
        }
        __syncthreads();
    }

#pragma unroll
    for (int i = 0; i < 4; i++) {
        float inv = 1.f / l_i[i];
        float* dst = g_O + ((size_t)((b * SQ + q0 + r0 + i) * HEADS + h)) * HEAD_DIM + cO;
        float4 v0 = make_float4(acc[i][0] * inv, acc[i][1] * inv, acc[i][2] * inv, acc[i][3] * inv);
        float4 v1 = make_float4(acc[i][4] * inv, acc[i][5] * inv, acc[i][6] * inv, acc[i][7] * inv);
        *(float4*)(dst)     = v0;
        *(float4*)(dst + 4) = v1;
    }
}

// ---------------- launch ---------------------------------------------------------
extern "C" void kernel_launch(void* const* d_in, const int* in_sizes, int n_in,
                              void* d_out, int out_size) {
    const float* x    = (const float*)d_in[0];
    const float* enc  = (const float*)d_in[1];
    const int*   mask = (const int*)d_in[2];
    const float* Wq   = (const float*)d_in[3];
    const float* Wk   = (const float*)d_in[4];
    const float* Wv   = (const float*)d_in[5];
    const float* Wo   = (const float*)d_in[6];
    float* out = (float*)d_out;

    float *q, *k, *v, *o;
    cudaGetSymbolAddress((void**)&q, g_Q);
    cudaGetSymbolAddress((void**)&k, g_K);
    cudaGetSymbolAddress((void**)&v, g_V);
    cudaGetSymbolAddress((void**)&o, g_O);

    rope_table_kernel<<<(SK * HALF_DIM + 255) / 256, 256>>>();

    cudaFuncSetAttribute(gemm_mma_kernel,
                         cudaFuncAttributeMaxDynamicSharedMemorySize, GM_SMEM);
    dim3 gg(HIDDEN / GM_TN, MROWS / GM_TM);   // (16, 32)
    gemm_mma_kernel<<<gg, 256, GM_SMEM>>>(x,   Wq, q, MROWS, HIDDEN, HIDDEN);
    gemm_mma_kernel<<<gg, 256, GM_SMEM>>>(enc, Wk, k, MROWS, HIDDEN, HIDDEN);
    gemm_mma_kernel<<<gg, 256, GM_SMEM>>>(enc, Wv, v, MROWS, HIDDEN, HIDDEN);

    long pairs = (long)BATCH * SQ * HEADS * HALF_DIM;
    int rb = (int)((pairs + 255) / 256);
    rope_apply_kernel<<<rb, 256>>>(q, SQ, pairs);
    rope_apply_kernel<<<rb, 256>>>(k, SK, pairs);

    cudaFuncSetAttribute(flash_attn_kernel,
                         cudaFuncAttributeMaxDynamicSharedMemorySize, FA_SMEM_BYTES);
    dim3 ga(BATCH * HEADS, SQ / FA_BM);
    flash_attn_kernel<<<ga, 256, FA_SMEM_BYTES>>>(mask);

    gemm_mma_kernel<<<gg, 256, GM_SMEM>>>(o, Wo, out, MROWS, HIDDEN, HIDDEN);
}

// round 5
// speedup vs baseline: 3.4728x; 2.1203x over previous
#include <cuda_runtime.h>
#include <math.h>
#include <stdint.h>

#define HIDDEN   2048
#define HEADS    16
#define HEAD_DIM 128
#define HALF_DIM 64
#define BATCH    2
#define SQ       2048
#define SK       2048
#define MROWS    (BATCH * SQ)   // 4096

// ---------------- scratch (device globals; no allocation allowed) ----------------
__device__ float g_Q[BATCH * SQ * HIDDEN];
__device__ float g_K[BATCH * SK * HIDDEN];
__device__ float g_V[BATCH * SK * HIDDEN];
__device__ float g_O[BATCH * SQ * HIDDEN];
__device__ float g_cos[SK * HALF_DIM];
__device__ float g_sin[SK * HALF_DIM];

// ================= helpers =================
__device__ __forceinline__ uint32_t smem_u32(const void* p) {
    uint32_t a;
    asm("{ .reg .u64 t; cvta.to.shared.u64 t, %1; cvt.u32.u64 %0, t; }" : "=r"(a) : "l"(p));
    return a;
}
__device__ __forceinline__ void cp16(uint32_t dst, const void* src) {
    asm volatile("cp.async.cg.shared.global [%0], [%1], 16;" :: "r"(dst), "l"(src));
}
__device__ __forceinline__ float to_tf32(float x) {
    float y;
    asm("cvt.rna.tf32.f32 %0, %1;" : "=f"(y) : "f"(x));
    return y;
}
__device__ __forceinline__ void mma_tf32(float* c, const float* a, const float* b) {
    asm volatile(
        "mma.sync.aligned.m16n8k8.row.col.f32.tf32.tf32.f32 "
        "{%0,%1,%2,%3}, {%4,%5,%6,%7}, {%8,%9}, {%0,%1,%2,%3};"
        : "+f"(c[0]), "+f"(c[1]), "+f"(c[2]), "+f"(c[3])
        : "f"(a[0]), "f"(a[1]), "f"(a[2]), "f"(a[3]),
          "f"(b[0]), "f"(b[1]));
}

// ---------------- RoPE table ----------------
__global__ void rope_table_kernel() {
    int i = blockIdx.x * blockDim.x + threadIdx.x;
    if (i >= SK * HALF_DIM) return;
    int s = i / HALF_DIM;
    int f = i - s * HALF_DIM;
    double inv = pow(10000.0, -(double)f / (double)HALF_DIM);
    double ang = (double)s * inv;
    g_cos[i] = (float)cos(ang);
    g_sin[i] = (float)sin(ang);
}

// ================= tf32 mma.sync GEMM: C[M,N] = A[M,K] * B[N,K]^T ===============
#define GM_TM 128
#define GM_TN 128
#define GM_TK 32
#define GM_LDS 36
#define GM_STG (GM_TM * GM_LDS)
#define GM_SMEM (4 * GM_STG * 4)

__global__ __launch_bounds__(256) void gemm_mma_kernel(
    const float* __restrict__ A, const float* __restrict__ Bm,
    float* __restrict__ C, int M, int N, int K)
{
    extern __shared__ float sm[];
    float* As = sm;
    float* Bs = sm + 2 * GM_STG;

    const int tid = threadIdx.x;
    const int wid = tid >> 5;
    const int lane = tid & 31;
    const int qr = lane >> 2;
    const int qc = lane & 3;
    const int m0 = blockIdx.y * GM_TM;
    const int n0 = blockIdx.x * GM_TN;
    const int wm = (wid & 3) * 32;
    const int wn = (wid >> 2) * 64;

    const uint32_t sa = smem_u32(As);
    const uint32_t sb = smem_u32(Bs);

    float acc[2][8][4];
#pragma unroll
    for (int i = 0; i < 2; i++)
#pragma unroll
        for (int j = 0; j < 8; j++)
#pragma unroll
            for (int t = 0; t < 4; t++) acc[i][j][t] = 0.f;

    auto load_stage = [&](int st, int kk) {
        uint32_t ab = sa + st * GM_STG * 4;
        uint32_t bb = sb + st * GM_STG * 4;
#pragma unroll
        for (int c = 0; c < 4; c++) {
            int e = tid + c * 256;
            int r = e >> 3, cx = e & 7;
            cp16(ab + r * 144 + cx * 16, A + (size_t)(m0 + r) * K + kk + cx * 4);
        }
#pragma unroll
        for (int c = 0; c < 4; c++) {
            int e = tid + c * 256;
            int r = e >> 3, cx = e & 7;
            cp16(bb + r * 144 + cx * 16, Bm + (size_t)(n0 + r) * K + kk + cx * 4);
        }
    };

    const int ITERS = K / GM_TK;
    load_stage(0, 0);
    asm volatile("cp.async.commit_group;");

    for (int it = 0; it < ITERS; it++) {
        if (it + 1 < ITERS) {
            load_stage((it + 1) & 1, (it + 1) * GM_TK);
            asm volatile("cp.async.commit_group;");
            asm volatile("cp.async.wait_group 1;" ::: "memory");
        } else {
            asm volatile("cp.async.wait_group 0;" ::: "memory");
        }
        __syncthreads();

        const float* at = As + (it & 1) * GM_STG;
        const float* bt = Bs + (it & 1) * GM_STG;

#pragma unroll
        for (int s = 0; s < 4; s++) {
            int kb = s * 8;
            float af[2][4], bf[8][2];
#pragma unroll
            for (int i = 0; i < 2; i++) {
                const float* p = at + (wm + i * 16 + qr) * GM_LDS + kb + qc;
                af[i][0] = to_tf32(p[0]);
                af[i][1] = to_tf32(p[8 * GM_LDS]);
                af[i][2] = to_tf32(p[4]);
                af[i][3] = to_tf32(p[8 * GM_LDS + 4]);
            }
#pragma unroll
            for (int j = 0; j < 8; j++) {
                const float* p = bt + (wn + j * 8 + qr) * GM_LDS + kb + qc;
                bf[j][0] = to_tf32(p[0]);
                bf[j][1] = to_tf32(p[4]);
            }
#pragma unroll
            for (int i = 0; i < 2; i++)
#pragma unroll
                for (int j = 0; j < 8; j++)
                    mma_tf32(acc[i][j], af[i], bf[j]);
        }
        __syncthreads();
    }

#pragma unroll
    for (int i = 0; i < 2; i++) {
        int rlo = m0 + wm + i * 16 + qr;
#pragma unroll
        for (int j = 0; j < 8; j++) {
            int col = n0 + wn + j * 8 + qc * 2;
            float2 v0 = make_float2(acc[i][j][0], acc[i][j][1]);
            float2 v1 = make_float2(acc[i][j][2], acc[i][j][3]);
            *(float2*)(C + (size_t)rlo * N + col)       = v0;
            *(float2*)(C + (size_t)(rlo + 8) * N + col) = v1;
        }
    }
}

// ---------------- RoPE apply ----------------
__global__ void rope_apply_kernel(float* __restrict__ buf, int S, long total_pairs) {
    long i = (long)blockIdx.x * blockDim.x + threadIdx.x;
    if (i >= total_pairs) return;
    int f = (int)(i & (HALF_DIM - 1));
    long t = i >> 6;
    int s = (int)((t / HEADS) % S);
    float c  = g_cos[s * HALF_DIM + f];
    float sn = g_sin[s * HALF_DIM + f];
    float2* p = (float2*)(buf + t * (size_t)HEAD_DIM) + f;
    float2 xv = *p;
    float2 ov;
    ov.x = xv.x * c - xv.y * sn;
    ov.y = xv.x * sn + xv.y * c;
    *p = ov;
}

// ================= flash attention via tf32 mma.sync =============================
// CTA: 128 q-rows of one (b,h). Iterate keys in 64-wide tiles.
// 8 warps; warp owns a 16-row q band (1 m-frag). Per-warp softmax state.
// Smem: Q[128][132], K[64][132], V[64][132] (all row-major, cp.async),
//       P[128][68], mask[2048].
#define FB_BM   128
#define FB_BN   64
#define FB_QKS  132        // Q/K/V row stride (floats)
#define FB_PS   68         // P row stride
#define FB_QF   (128 * FB_QKS)
#define FB_KF   (64 * FB_QKS)
#define FB_VF   (64 * FB_QKS)
#define FB_PF   (128 * FB_PS)
#define FB_SMEM ((FB_QF + FB_KF + FB_VF + FB_PF) * 4)   // 169984 bytes

__global__ __launch_bounds__(256, 1) void flash_mma_kernel(const int* __restrict__ mask) {
    extern __shared__ float sm[];
    float* Qs = sm;
    float* Ks = Qs + FB_QF;
    float* Vs = Ks + FB_KF;
    float* Ps = Vs + FB_VF;
    __shared__ int msAll[SK];

    const int bh = blockIdx.x;
    const int b  = bh / HEADS;
    const int h  = bh - b * HEADS;
    const int q0 = blockIdx.y * FB_BM;
    const int tid  = threadIdx.x;
    const int wid  = tid >> 5;
    const int lane = tid & 31;
    const int qr = lane >> 2;
    const int qc = lane & 3;
    const int wm = wid * 16;                 // warp's q band
    const float rscale = 0.08838834764831845f;

    const uint32_t sQ = smem_u32(Qs);
    const uint32_t sK = smem_u32(Ks);
    const uint32_t sV = smem_u32(Vs);

    const size_t headQ = ((size_t)(b * SQ + q0) * HEADS + h) * HEAD_DIM;
    const size_t headKV = ((size_t)(b * SK) * HEADS + h) * HEAD_DIM;
    const size_t rowStride = (size_t)HEADS * HEAD_DIM;   // 2048

    // ---- async loaders ----
    auto load_K = [&](int kt) {
#pragma unroll
        for (int c = 0; c < 8; c++) {
            int e = tid + c * 256;
            int r = e >> 5, d4 = (e & 31) * 4;
            cp16(sK + (r * FB_QKS + d4) * 4,
                 g_K + headKV + (size_t)(kt * FB_BN + r) * rowStride + d4);
        }
    };
    auto load_V = [&](int kt) {
#pragma unroll
        for (int c = 0; c < 8; c++) {
            int e = tid + c * 256;
            int r = e >> 5, d4 = (e & 31) * 4;
            cp16(sV + (r * FB_QKS + d4) * 4,
                 g_V + headKV + (size_t)(kt * FB_BN + r) * rowStride + d4);
        }
    };

    // ---- prologue: Q + K0 (group A), V0 (group B), mask ----
#pragma unroll
    for (int c = 0; c < 16; c++) {
        int e = tid + c * 256;
        int r = e >> 5, d4 = (e & 31) * 4;
        cp16(sQ + (r * FB_QKS + d4) * 4, g_Q + headQ + (size_t)r * rowStride + d4);
    }
    load_K(0);
    asm volatile("cp.async.commit_group;");
    load_V(0);
    asm volatile("cp.async.commit_group;");
    for (int i = tid; i < SK; i += 256) msAll[i] = mask[b * SK + i];

    asm volatile("cp.async.wait_group 1;" ::: "memory");
    __syncthreads();

    // ---- state ----
    float m0v = -1e30f, m1v = -1e30f;
    float l0 = 0.f, l1 = 0.f;
    float Oacc[16][4];
#pragma unroll
    for (int n = 0; n < 16; n++)
#pragma unroll
        for (int t = 0; t < 4; t++) Oacc[n][t] = 0.f;

    const int NIT = SK / FB_BN;   // 32

    for (int it = 0; it < NIT; it++) {
        const int kO = it * FB_BN;

        // ===== S phase: S[16 x 64] = Q_band * K^T =====
        float sacc[8][4];
#pragma unroll
        for (int j = 0; j < 8; j++)
#pragma unroll
            for (int t = 0; t < 4; t++) sacc[j][t] = 0.f;

#pragma unroll
        for (int ks = 0; ks < 16; ks++) {
            int kb = ks * 8;
            float a[4];
            const float* ap = Qs + (wm + qr) * FB_QKS + kb + qc;
            a[0] = to_tf32(ap[0]);
            a[1] = to_tf32(ap[8 * FB_QKS]);
            a[2] = to_tf32(ap[4]);
            a[3] = to_tf32(ap[8 * FB_QKS + 4]);
#pragma unroll
            for (int j = 0; j < 8; j++) {
                const float* bp = Ks + (j * 8 + qr) * FB_QKS + kb + qc;
                float bfr[2];
                bfr[0] = to_tf32(bp[0]);
                bfr[1] = to_tf32(bp[4]);
                mma_tf32(sacc[j], a, bfr);
            }
        }
        __syncthreads();                       // all warps done with Ks
        if (it + 1 < NIT) {
            load_K(it + 1);                    // overlaps softmax + PV
            asm volatile("cp.async.commit_group;");
        }

        // ===== softmax (per-warp rows wm+qr, wm+qr+8) =====
        float mx0 = -1e30f, mx1 = -1e30f;
#pragma unroll
        for (int j = 0; j < 8; j++) {
            int c0 = j * 8 + 2 * qc;
            int k0m = msAll[kO + c0];
            int k1m = msAll[kO + c0 + 1];
            float v0 = k0m ? sacc[j][0] * rscale : -1e30f;
            float v1 = k1m ? sacc[j][1] * rscale : -1e30f;
            float v2 = k0m ? sacc[j][2] * rscale : -1e30f;
            float v3 = k1m ? sacc[j][3] * rscale : -1e30f;
            sacc[j][0] = v0; sacc[j][1] = v1; sacc[j][2] = v2; sacc[j][3] = v3;
            mx0 = fmaxf(mx0, fmaxf(v0, v1));
            mx1 = fmaxf(mx1, fmaxf(v2, v3));
        }
        mx0 = fmaxf(mx0, __shfl_xor_sync(0xffffffffu, mx0, 1));
        mx0 = fmaxf(mx0, __shfl_xor_sync(0xffffffffu, mx0, 2));
        mx1 = fmaxf(mx1, __shfl_xor_sync(0xffffffffu, mx1, 1));
        mx1 = fmaxf(mx1, __shfl_xor_sync(0xffffffffu, mx1, 2));

        float mn0 = fmaxf(m0v, mx0);
        float mn1 = fmaxf(m1v, mx1);
        float corr0 = expf(m0v - mn0);
        float corr1 = expf(m1v - mn1);
        m0v = mn0; m1v = mn1;

        float sum0 = 0.f, sum1 = 0.f;
#pragma unroll
        for (int j = 0; j < 8; j++) {
            float p0 = expf(sacc[j][0] - mn0);
            float p1 = expf(sacc[j][1] - mn0);
            float p2 = expf(sacc[j][2] - mn1);
            float p3 = expf(sacc[j][3] - mn1);
            sum0 += p0 + p1;
            sum1 += p2 + p3;
            int c0 = j * 8 + 2 * qc;
            *(float2*)&Ps[(wm + qr) * FB_PS + c0]     = make_float2(p0, p1);
            *(float2*)&Ps[(wm + qr + 8) * FB_PS + c0] = make_float2(p2, p3);
        }
        sum0 += __shfl_xor_sync(0xffffffffu, sum0, 1);
        sum0 += __shfl_xor_sync(0xffffffffu, sum0, 2);
        sum1 += __shfl_xor_sync(0xffffffffu, sum1, 1);
        sum1 += __shfl_xor_sync(0xffffffffu, sum1, 2);
        l0 = l0 * corr0 + sum0;
        l1 = l1 * corr1 + sum1;

#pragma unroll
        for (int n = 0; n < 16; n++) {
            Oacc[n][0] *= corr0; Oacc[n][1] *= corr0;
            Oacc[n][2] *= corr1; Oacc[n][3] *= corr1;
        }
        __syncwarp();                          // P band written (own warp only)

        // wait V_it (one group may still be pending: K_{it+1})
        if (it + 1 < NIT) {
            asm volatile("cp.async.wait_group 1;" ::: "memory");
        } else {
            asm volatile("cp.async.wait_group 0;" ::: "memory");
        }
        __syncthreads();

        // ===== PV phase: O_band += P_band * V =====
#pragma unroll
        for (int ks = 0; ks < 8; ks++) {
            int kb = ks * 8;
            float a[4];
            const float* ap = Ps + (wm + qr) * FB_PS + kb + qc;
            a[0] = ap[0];
            a[1] = ap[8 * FB_PS];
            a[2] = ap[4];
            a[3] = ap[8 * FB_PS + 4];
#pragma unroll
            for (int n = 0; n < 16; n++) {
                const float* bp = Vs + (kb + qc) * FB_QKS + n * 8 + qr;
                float bfr[2];
                bfr[0] = bp[0];
                bfr[1] = bp[4 * FB_QKS];
                mma_tf32(Oacc[n], a, bfr);
            }
        }
        __syncthreads();                       // all warps done with Vs
        if (it + 1 < NIT) {
            load_V(it + 1);                    // overlaps next S phase
            asm volatile("cp.async.commit_group;");
        }
        // next S phase needs K_{it+1}: pending = {K_{it+1}, V_{it+1}}
        if (it + 1 < NIT) {
            asm volatile("cp.async.wait_group 1;" ::: "memory");
            __syncthreads();
        }
    }

    // ---- epilogue ----
    float inv0 = 1.f / l0;
    float inv1 = 1.f / l1;
    const int row0 = q0 + wm + qr;
    float* d0 = g_O + ((size_t)(b * SQ + row0) * HEADS + h) * HEAD_DIM;
    float* d1 = d0 + 8 * rowStride;
#pragma unroll
    for (int n = 0; n < 16; n++) {
        int col = n * 8 + 2 * qc;
        *(float2*)(d0 + col) = make_float2(Oacc[n][0] * inv0, Oacc[n][1] * inv0);
        *(float2*)(d1 + col) = make_float2(Oacc[n][2] * inv1, Oacc[n][3] * inv1);
    }
}

// ---------------- launch ---------------------------------------------------------
extern "C" void kernel_launch(void* const* d_in, const int* in_sizes, int n_in,
                              void* d_out, int out_size) {
    const float* x    = (const float*)d_in[0];
    const float* enc  = (const float*)d_in[1];
    const int*   mask = (const int*)d_in[2];
    const float* Wq   = (const float*)d_in[3];
    const float* Wk   = (const float*)d_in[4];
    const float* Wv   = (const float*)d_in[5];
    const float* Wo   = (const float*)d_in[6];
    float* out = (float*)d_out;

    float *q, *k, *v, *o;
    cudaGetSymbolAddress((void**)&q, g_Q);
    cudaGetSymbolAddress((void**)&k, g_K);
    cudaGetSymbolAddress((void**)&v, g_V);
    cudaGetSymbolAddress((void**)&o, g_O);

    rope_table_kernel<<<(SK * HALF_DIM + 255) / 256, 256>>>();

    cudaFuncSetAttribute(gemm_mma_kernel,
                         cudaFuncAttributeMaxDynamicSharedMemorySize, GM_SMEM);
    dim3 gg(HIDDEN / GM_TN, MROWS / GM_TM);
    gemm_mma_kernel<<<gg, 256, GM_SMEM>>>(x,   Wq, q, MROWS, HIDDEN, HIDDEN);
    gemm_mma_kernel<<<gg, 256, GM_SMEM>>>(enc, Wk, k, MROWS, HIDDEN, HIDDEN);
    gemm_mma_kernel<<<gg, 256, GM_SMEM>>>(enc, Wv, v, MROWS, HIDDEN, HIDDEN);

    long pairs = (long)BATCH * SQ * HEADS * HALF_DIM;
    int rb = (int)((pairs + 255) / 256);
    rope_apply_kernel<<<rb, 256>>>(q, SQ, pairs);
    rope_apply_kernel<<<rb, 256>>>(k, SK, pairs);

    cudaFuncSetAttribute(flash_mma_kernel,
                         cudaFuncAttributeMaxDynamicSharedMemorySize, FB_SMEM);
    dim3 ga(BATCH * HEADS, SQ / FB_BM);   // (32, 16)
    flash_mma_kernel<<<ga, 256, FB_SMEM>>>(mask);

    gemm_mma_kernel<<<gg, 256, GM_SMEM>>>(o, Wo, out, MROWS, HIDDEN, HIDDEN);
}